// round 1
// baseline (speedup 1.0000x reference)
#include <cuda_runtime.h>
#include <cstdint>

#define BATCH   256
#define NLAB    30000
#define NEDGE   29999
#define HID     1024
#define SMEM_BYTES (NLAB * 4)

// Global accumulators + scratch (no allocations allowed in kernel_launch).
__device__ double g_acc[3];          // [0]=bce sum, [1]=rec sum, [2]=prob sum
__device__ int2   g_edges[NEDGE];    // packed (parent, child) as int32
__device__ int    g_nonzero_odd;     // dtype detection flag

// ---------------------------------------------------------------------------
// init: zero accumulators and detection flag (fresh every launch -> graph-safe,
// deterministic).
__global__ void k_init() {
    if (threadIdx.x == 0) {
        g_acc[0] = 0.0; g_acc[1] = 0.0; g_acc[2] = 0.0;
        g_nonzero_odd = 0;
    }
}

// ---------------------------------------------------------------------------
// dtype detection: interpret index buffers as 32-bit words. If the underlying
// data is int64 (values < 30000), every odd word within the first NEDGE words
// is zero. If int32, odd words are random indices (virtually surely nonzero).
// Only scans the first NEDGE words -> always in bounds for either dtype.
__global__ void k_detect(const unsigned int* __restrict__ p,
                         const unsigned int* __restrict__ c) {
    int i = blockIdx.x * blockDim.x + threadIdx.x;
    if (i < NEDGE && (i & 1)) {
        if ((p[i] | c[i]) != 0u) atomicExch(&g_nonzero_odd, 1);
    }
}

// pack (parent, child) into int2 (int32). Reads dtype flag set by k_detect.
__global__ void k_pack(const void* __restrict__ p, const void* __restrict__ c) {
    int i = blockIdx.x * blockDim.x + threadIdx.x;
    if (i >= NEDGE) return;
    int pv, cv;
    if (g_nonzero_odd == 0) {  // int64
        pv = (int)((const long long*)p)[i];
        cv = (int)((const long long*)c)[i];
    } else {                   // int32
        pv = ((const int*)p)[i];
        cv = ((const int*)c)[i];
    }
    g_edges[i] = make_int2(pv, cv);
}

// ---------------------------------------------------------------------------
// block reduction helper: returns total in thread 0.
__device__ __forceinline__ float block_reduce(float v, float* sbuf) {
    int lane = threadIdx.x & 31;
    int warp = threadIdx.x >> 5;
    #pragma unroll
    for (int o = 16; o > 0; o >>= 1) v += __shfl_down_sync(0xFFFFFFFFu, v, o);
    if (lane == 0) sbuf[warp] = v;
    __syncthreads();
    int nwarp = (blockDim.x + 31) >> 5;
    v = 0.f;
    if (warp == 0) {
        v = (lane < nwarp) ? sbuf[lane] : 0.f;
        #pragma unroll
        for (int o = 16; o > 0; o >>= 1) v += __shfl_down_sync(0xFFFFFFFFu, v, o);
    }
    return v;
}

// ---------------------------------------------------------------------------
// Fused BCE + prob_reg. One CTA per batch row:
//   phase 1: stream logits+targets row, accumulate softplus(x)-x*t, and write
//            sigmoid(x) into shared memory (row fits: 117 KB).
//   phase 2: gather sigmoid values from smem per edge, accumulate relu(diff).
__global__ void __launch_bounds__(1024) k_bce_prob(
    const float* __restrict__ logits, const float* __restrict__ targets)
{
    extern __shared__ float s_sig[];        // NLAB floats
    __shared__ float sbuf[32];

    int b = blockIdx.x;
    const float4* l4 = (const float4*)(logits  + (size_t)b * NLAB);
    const float4* t4 = (const float4*)(targets + (size_t)b * NLAB);
    float4* s4 = (float4*)s_sig;

    float bacc = 0.f;
    for (int i = threadIdx.x; i < NLAB / 4; i += blockDim.x) {
        float4 x = l4[i];
        float4 t = t4[i];
        float4 sg;
        {
            float ax = fabsf(x.x); float e = __expf(-ax);
            bacc += fmaxf(x.x, 0.f) + __logf(1.f + e) - x.x * t.x;
            float r = __fdividef(1.f, 1.f + e);
            sg.x = (x.x >= 0.f) ? r : e * r;
        }
        {
            float ax = fabsf(x.y); float e = __expf(-ax);
            bacc += fmaxf(x.y, 0.f) + __logf(1.f + e) - x.y * t.y;
            float r = __fdividef(1.f, 1.f + e);
            sg.y = (x.y >= 0.f) ? r : e * r;
        }
        {
            float ax = fabsf(x.z); float e = __expf(-ax);
            bacc += fmaxf(x.z, 0.f) + __logf(1.f + e) - x.z * t.z;
            float r = __fdividef(1.f, 1.f + e);
            sg.z = (x.z >= 0.f) ? r : e * r;
        }
        {
            float ax = fabsf(x.w); float e = __expf(-ax);
            bacc += fmaxf(x.w, 0.f) + __logf(1.f + e) - x.w * t.w;
            float r = __fdividef(1.f, 1.f + e);
            sg.w = (x.w >= 0.f) ? r : e * r;
        }
        s4[i] = sg;
    }
    __syncthreads();

    float pacc = 0.f;
    for (int e = threadIdx.x; e < NEDGE; e += blockDim.x) {
        int2 pc = g_edges[e];
        float d = s_sig[pc.y] - s_sig[pc.x];   // child - parent
        pacc += fmaxf(d, 0.f);
    }

    float btot = block_reduce(bacc, sbuf);
    if (threadIdx.x == 0) atomicAdd(&g_acc[0], (double)btot);
    __syncthreads();  // sbuf reuse
    float ptot = block_reduce(pacc, sbuf);
    if (threadIdx.x == 0) atomicAdd(&g_acc[2], (double)ptot);
}

// ---------------------------------------------------------------------------
// rec_reg: grid-stride over edges; one CTA (256 threads) covers one edge's
// 1024-dim diff per iteration via float4 loads. Single double atomic per CTA.
__global__ void __launch_bounds__(256) k_rec(const float* __restrict__ params)
{
    __shared__ float sbuf[32];
    float acc = 0.f;
    for (int e = blockIdx.x; e < NEDGE; e += gridDim.x) {
        int2 pc = g_edges[e];
        const float4* pp = (const float4*)(params + (size_t)pc.x * HID);
        const float4* cc = (const float4*)(params + (size_t)pc.y * HID);
        float4 a = pp[threadIdx.x];
        float4 c = cc[threadIdx.x];
        float dx = a.x - c.x, dy = a.y - c.y, dz = a.z - c.z, dw = a.w - c.w;
        acc += dx * dx + dy * dy + dz * dz + dw * dw;
    }
    float tot = block_reduce(acc, sbuf);
    if (threadIdx.x == 0) atomicAdd(&g_acc[1], (double)tot);
}

// ---------------------------------------------------------------------------
__global__ void k_final(float* __restrict__ out) {
    if (threadIdx.x == 0) {
        double bce  = g_acc[0] / ((double)BATCH * (double)NLAB);
        double rec  = 0.5 * g_acc[1];
        double prob = g_acc[2];
        out[0] = (float)(bce + 1e-4 * rec + 1e-4 * prob);
    }
}

// ---------------------------------------------------------------------------
extern "C" void kernel_launch(void* const* d_in, const int* in_sizes, int n_in,
                              void* d_out, int out_size)
{
    const float* logits  = (const float*)d_in[0];
    const float* targets = (const float*)d_in[1];
    const float* params  = (const float*)d_in[2];
    const void*  parent  = d_in[3];
    const void*  child   = d_in[4];

    cudaFuncSetAttribute(k_bce_prob,
                         cudaFuncAttributeMaxDynamicSharedMemorySize,
                         SMEM_BYTES);

    k_init<<<1, 1>>>();
    k_detect<<<(NEDGE + 255) / 256, 256>>>((const unsigned int*)parent,
                                           (const unsigned int*)child);
    k_pack<<<(NEDGE + 255) / 256, 256>>>(parent, child);
    k_bce_prob<<<BATCH, 1024, SMEM_BYTES>>>(logits, targets);
    k_rec<<<1216, 256>>>(params);
    k_final<<<1, 1>>>((float*)d_out);
}

// round 2
// speedup vs baseline: 1.2317x; 1.2317x over previous
#include <cuda_runtime.h>
#include <cuda_fp16.h>
#include <cstdint>

#define BATCH   256
#define NLAB    30000
#define NEDGE   29999
#define HID     1024
#define MAIN_GRID 296              // 148 SMs * 2 CTAs -> exactly one wave
#define SMEM_BYTES (NLAB * 2)      // fp16 sigmoid row

// Global accumulators + scratch (no allocations allowed anywhere).
__device__ double g_acc[3];          // [0]=bce sum, [1]=rec sum, [2]=prob sum
__device__ int2   g_edges[NEDGE];    // packed (parent, child) as int32
__device__ int    g_nonzero_odd;     // dtype detection flag
__device__ int    g_ctr;             // rec edge work-stealing counter

// ---------------------------------------------------------------------------
__global__ void k_init() {
    if (threadIdx.x == 0) {
        g_acc[0] = 0.0; g_acc[1] = 0.0; g_acc[2] = 0.0;
        g_nonzero_odd = 0;
        g_ctr = 0;
    }
}

// ---------------------------------------------------------------------------
// dtype detection: if underlying data is int64 (values < 30000), every odd
// 32-bit word within the first NEDGE words is zero. int32 random indices are
// virtually surely nonzero somewhere odd. Always in-bounds for both dtypes.
__global__ void k_detect(const unsigned int* __restrict__ p,
                         const unsigned int* __restrict__ c) {
    int i = blockIdx.x * blockDim.x + threadIdx.x;
    if (i < NEDGE && (i & 1)) {
        if ((p[i] | c[i]) != 0u) atomicExch(&g_nonzero_odd, 1);
    }
}

__global__ void k_pack(const void* __restrict__ p, const void* __restrict__ c) {
    int i = blockIdx.x * blockDim.x + threadIdx.x;
    if (i >= NEDGE) return;
    int pv, cv;
    if (g_nonzero_odd == 0) {  // int64
        pv = (int)((const long long*)p)[i];
        cv = (int)((const long long*)c)[i];
    } else {                   // int32
        pv = ((const int*)p)[i];
        cv = ((const int*)c)[i];
    }
    g_edges[i] = make_int2(pv, cv);
}

// ---------------------------------------------------------------------------
__device__ __forceinline__ float block_reduce(float v, float* sbuf) {
    int lane = threadIdx.x & 31;
    int warp = threadIdx.x >> 5;
    #pragma unroll
    for (int o = 16; o > 0; o >>= 1) v += __shfl_down_sync(0xFFFFFFFFu, v, o);
    if (lane == 0) sbuf[warp] = v;
    __syncthreads();
    int nwarp = blockDim.x >> 5;
    v = 0.f;
    if (warp == 0) {
        v = (lane < nwarp) ? sbuf[lane] : 0.f;
        #pragma unroll
        for (int o = 16; o > 0; o >>= 1) v += __shfl_down_sync(0xFFFFFFFFu, v, o);
    }
    return v;
}

__device__ __forceinline__ float fast_tanh(float x) {
    float r;
    asm("tanh.approx.f32 %0, %1;" : "=f"(r) : "f"(x));
    return r;
}

// sigmoid of |x| and sigmoid of x, plus softplus, with 2 MUFU ops total.
__device__ __forceinline__ void sig_sp(float x, float t_tgt,
                                       float& bacc, float& sig) {
    float a = fabsf(x);
    float th = fast_tanh(0.5f * a);        // MUFU.TANH
    float u  = fmaf(0.5f, th, 0.5f);       // sigmoid(|x|), in [0.5, 1]
    float sp = fmaxf(x, 0.f) - __logf(u);  // softplus(x); MUFU.LG2
    bacc += sp - x * t_tgt;
    sig = (x >= 0.f) ? u : (1.f - u);
}

// ---------------------------------------------------------------------------
// Fused single-wave kernel. Blocks [0, BATCH): bce + prob for one batch row
// (sigmoid row cached fp16 in smem), then fall through to rec work stealing.
// Blocks [BATCH, MAIN_GRID): rec work stealing from the start.
__global__ void __launch_bounds__(1024, 2) k_main(
    const float* __restrict__ logits, const float* __restrict__ targets,
    const float* __restrict__ params)
{
    extern __shared__ __half s_sig[];      // NLAB fp16 sigmoids
    __shared__ float sbuf[32];
    __shared__ int   s_base;

    int tid = threadIdx.x;
    int b   = blockIdx.x;

    if (b < BATCH) {
        const float4* l4 = (const float4*)(logits  + (size_t)b * NLAB);
        const float4* t4 = (const float4*)(targets + (size_t)b * NLAB);

        float bacc = 0.f;
        for (int i = tid; i < NLAB / 4; i += 1024) {
            float4 x = __ldcs(l4 + i);     // streamed: don't evict params from L2
            float4 t = __ldcs(t4 + i);
            float s0, s1, s2, s3;
            sig_sp(x.x, t.x, bacc, s0);
            sig_sp(x.y, t.y, bacc, s1);
            sig_sp(x.z, t.z, bacc, s2);
            sig_sp(x.w, t.w, bacc, s3);
            __half2 h01 = __floats2half2_rn(s0, s1);
            __half2 h23 = __floats2half2_rn(s2, s3);
            uint2 pk;
            pk.x = *(unsigned int*)&h01;
            pk.y = *(unsigned int*)&h23;
            ((uint2*)s_sig)[i] = pk;
        }
        __syncthreads();

        float pacc = 0.f;
        for (int e = tid; e < NEDGE; e += 1024) {
            int2 pc = g_edges[e];
            float d = __half2float(s_sig[pc.y]) - __half2float(s_sig[pc.x]);
            pacc += fmaxf(d, 0.f);
        }

        float bt = block_reduce(bacc, sbuf);
        if (tid == 0) atomicAdd(&g_acc[0], (double)bt);
        __syncthreads();
        float pt = block_reduce(pacc, sbuf);
        if (tid == 0) atomicAdd(&g_acc[2], (double)pt);
        __syncthreads();
    }

    // ---- rec_reg via global work stealing (8 edges per fetch) ----
    int sub = tid >> 8;        // 0..3 : edge slot within a round
    int ln  = tid & 255;       // float4 lane within the 1024-dim row
    float racc = 0.f;
    for (;;) {
        if (tid == 0) s_base = atomicAdd(&g_ctr, 8);
        __syncthreads();
        int base = s_base;
        if (base >= NEDGE) break;
        #pragma unroll
        for (int k = 0; k < 2; k++) {
            int e = base + k * 4 + sub;
            if (e < NEDGE) {
                int2 pc = g_edges[e];
                float4 a = ((const float4*)(params + (size_t)pc.x * HID))[ln];
                float4 c = ((const float4*)(params + (size_t)pc.y * HID))[ln];
                float dx = a.x - c.x, dy = a.y - c.y;
                float dz = a.z - c.z, dw = a.w - c.w;
                racc += dx * dx + dy * dy + dz * dz + dw * dw;
            }
        }
        __syncthreads();
    }
    float rt = block_reduce(racc, sbuf);
    if (tid == 0) atomicAdd(&g_acc[1], (double)rt);
}

// ---------------------------------------------------------------------------
__global__ void k_final(float* __restrict__ out) {
    if (threadIdx.x == 0) {
        double bce  = g_acc[0] / ((double)BATCH * (double)NLAB);
        double rec  = 0.5 * g_acc[1];
        double prob = g_acc[2];
        out[0] = (float)(bce + 1e-4 * rec + 1e-4 * prob);
    }
}

// ---------------------------------------------------------------------------
extern "C" void kernel_launch(void* const* d_in, const int* in_sizes, int n_in,
                              void* d_out, int out_size)
{
    const float* logits  = (const float*)d_in[0];
    const float* targets = (const float*)d_in[1];
    const float* params  = (const float*)d_in[2];
    const void*  parent  = d_in[3];
    const void*  child   = d_in[4];

    cudaFuncSetAttribute(k_main,
                         cudaFuncAttributeMaxDynamicSharedMemorySize,
                         SMEM_BYTES);

    k_init<<<1, 1>>>();
    k_detect<<<(NEDGE + 255) / 256, 256>>>((const unsigned int*)parent,
                                           (const unsigned int*)child);
    k_pack<<<(NEDGE + 255) / 256, 256>>>(parent, child);
    k_main<<<MAIN_GRID, 1024, SMEM_BYTES>>>(logits, targets, params);
    k_final<<<1, 1>>>((float*)d_out);
}

// round 4
// speedup vs baseline: 1.4435x; 1.1720x over previous
#include <cuda_runtime.h>
#include <cuda_fp16.h>
#include <cstdint>

#define BATCH     256
#define NLAB      30000
#define NEDGE     29999
#define NEDGE_PAD 30016              // multiple of 4; pad edges are (0,0) -> contribute 0
#define HID       1024
#define NBLK      444               // 148 SMs * 3 CTAs -> one wave
#define BLKT      512
#define SMEM_BYTES (NLAB * 2)        // fp16 sigmoid row

// Persistent device state. Invariant: every kernel_launch leaves these in their
// load-time state (g_acc=0, g_ctr=0, g_done=0), restored by the last CTA.
__device__ double       g_acc[3];           // [0]=bce, [1]=rec, [2]=prob
__device__ unsigned int g_edges[NEDGE_PAD]; // parent | (child<<16)
__device__ int          g_ctr;              // rec edge steal counter
__device__ unsigned int g_done;             // finished-CTA counter

// ---------------------------------------------------------------------------
// Single-CTA: detect index dtype locally, then pack all edges.
// If data is int64 (<30000), every odd 32-bit word is 0; 1024 random int32
// words being all-zero has probability ~0.
__global__ void __launch_bounds__(1024) k_pack(const void* __restrict__ p,
                                               const void* __restrict__ c)
{
    __shared__ int s_flag;
    int tid = threadIdx.x;
    if (tid == 0) s_flag = 0;
    __syncthreads();

    const unsigned int* pw = (const unsigned int*)p;
    const unsigned int* cw = (const unsigned int*)c;
    int i = 2 * tid + 1;                  // odd words, all < NEDGE
    if (i < NEDGE) {
        if ((pw[i] | cw[i]) != 0u) s_flag = 1;   // benign race
    }
    __syncthreads();
    bool is64 = (s_flag == 0);

    for (int e = tid; e < NEDGE_PAD; e += 1024) {
        unsigned int pk = 0;
        if (e < NEDGE) {
            unsigned int pv, cv;
            if (is64) {
                pv = (unsigned int)((const unsigned long long*)p)[e];
                cv = (unsigned int)((const unsigned long long*)c)[e];
            } else {
                pv = pw[e];
                cv = cw[e];
            }
            pk = pv | (cv << 16);
        }
        g_edges[e] = pk;
    }
}

// ---------------------------------------------------------------------------
__device__ __forceinline__ float block_reduce(float v, float* sbuf) {
    int lane = threadIdx.x & 31;
    int warp = threadIdx.x >> 5;
    #pragma unroll
    for (int o = 16; o > 0; o >>= 1) v += __shfl_down_sync(0xFFFFFFFFu, v, o);
    if (lane == 0) sbuf[warp] = v;
    __syncthreads();
    v = 0.f;
    if (warp == 0) {
        v = (lane < (BLKT >> 5)) ? sbuf[lane] : 0.f;
        #pragma unroll
        for (int o = 16; o > 0; o >>= 1) v += __shfl_down_sync(0xFFFFFFFFu, v, o);
    }
    return v;
}

__device__ __forceinline__ float fast_tanh(float x) {
    float r;
    asm("tanh.approx.f32 %0, %1;" : "=f"(r) : "f"(x));
    return r;
}

// softplus + sigmoid with 2 MUFU ops (tanh, lg2).
__device__ __forceinline__ void sig_sp(float x, float t_tgt,
                                       float& bacc, float& sig) {
    float a  = fabsf(x);
    float th = fast_tanh(0.5f * a);
    float u  = fmaf(0.5f, th, 0.5f);        // sigmoid(|x|) in [0.5, 1]
    bacc += fmaxf(x, 0.f) - __logf(u) - x * t_tgt;
    sig = (x >= 0.f) ? u : (1.f - u);
}

// ---------------------------------------------------------------------------
// Single-wave fused kernel. Blocks [0,BATCH): bce+prob for one batch row,
// then join rec work stealing. Blocks [BATCH,NBLK): rec from the start.
// Last CTA to finish writes the output and resets all device globals.
__global__ void __launch_bounds__(BLKT, 3) k_main(
    const float* __restrict__ logits, const float* __restrict__ targets,
    const float* __restrict__ params, float* __restrict__ out)
{
    extern __shared__ __half s_sig[];       // NLAB fp16 sigmoids
    __shared__ float sbuf[BLKT >> 5];

    int tid  = threadIdx.x;
    int lane = tid & 31;
    int b    = blockIdx.x;

    if (b < BATCH) {
        const float4* l4 = (const float4*)(logits  + (size_t)b * NLAB);
        const float4* t4 = (const float4*)(targets + (size_t)b * NLAB);

        float bacc = 0.f;
        for (int i = tid; i < NLAB / 4; i += BLKT) {
            float4 x = __ldcs(l4 + i);      // streamed: keep params L2-resident
            float4 t = __ldcs(t4 + i);
            float s0, s1, s2, s3;
            sig_sp(x.x, t.x, bacc, s0);
            sig_sp(x.y, t.y, bacc, s1);
            sig_sp(x.z, t.z, bacc, s2);
            sig_sp(x.w, t.w, bacc, s3);
            __half2 h01 = __floats2half2_rn(s0, s1);
            __half2 h23 = __floats2half2_rn(s2, s3);
            uint2 pk;
            pk.x = *(unsigned int*)&h01;
            pk.y = *(unsigned int*)&h23;
            ((uint2*)s_sig)[i] = pk;
        }
        __syncthreads();

        // prob: 4 packed edges per uint4, no bounds checks (padded).
        float pacc = 0.f;
        const uint4* ge4 = (const uint4*)g_edges;
        for (int i = tid; i < NEDGE_PAD / 4; i += BLKT) {
            uint4 q = ge4[i];
            #pragma unroll
            for (int k = 0; k < 4; k++) {
                unsigned int pk = (&q.x)[k];
                float sp = __half2float(s_sig[pk & 0xFFFFu]);
                float sc = __half2float(s_sig[pk >> 16]);
                pacc += fmaxf(sc - sp, 0.f);
            }
        }

        float bt = block_reduce(bacc, sbuf);
        if (tid == 0) atomicAdd(&g_acc[0], (double)bt);
        __syncthreads();
        float pt = block_reduce(pacc, sbuf);
        if (tid == 0) atomicAdd(&g_acc[2], (double)pt);
        __syncthreads();
    }

    // ---- rec: warp-autonomous work stealing, 4 edges per steal ----
    float racc = 0.f;
    for (;;) {
        int base = 0;
        if (lane == 0) base = atomicAdd(&g_ctr, 4);
        base = __shfl_sync(0xFFFFFFFFu, base, 0);
        if (base >= NEDGE_PAD) break;
        #pragma unroll
        for (int k = 0; k < 4; k++) {       // NEDGE_PAD % 4 == 0 -> in bounds
            unsigned int pk = g_edges[base + k];
            const float4* pa = (const float4*)(params + (size_t)(pk & 0xFFFFu) * HID);
            const float4* pb = (const float4*)(params + (size_t)(pk >> 16) * HID);
            #pragma unroll
            for (int j = 0; j < 8; j++) {
                float4 a = pa[lane + 32 * j];
                float4 c = pb[lane + 32 * j];
                float dx = a.x - c.x, dy = a.y - c.y;
                float dz = a.z - c.z, dw = a.w - c.w;
                racc += dx * dx + dy * dy + dz * dz + dw * dw;
            }
        }
    }
    __syncthreads();                         // all warps done stealing
    float rt = block_reduce(racc, sbuf);
    if (tid == 0) atomicAdd(&g_acc[1], (double)rt);

    // ---- finalize: last CTA writes out and resets globals ----
    if (tid == 0) {
        __threadfence();                     // publish this CTA's atomics
        unsigned int d = atomicAdd(&g_done, 1u);
        if (d == NBLK - 1) {
            __threadfence();                 // acquire others' g_acc
            volatile double* acc = g_acc;
            double bce  = acc[0] / ((double)BATCH * (double)NLAB);
            double rec  = 0.5 * acc[1];
            double prob = acc[2];
            out[0] = (float)(bce + 1e-4 * rec + 1e-4 * prob);
            g_acc[0] = 0.0; g_acc[1] = 0.0; g_acc[2] = 0.0;
            g_ctr  = 0;
            g_done = 0u;
            __threadfence();
        }
    }
}

// ---------------------------------------------------------------------------
extern "C" void kernel_launch(void* const* d_in, const int* in_sizes, int n_in,
                              void* d_out, int out_size)
{
    const float* logits  = (const float*)d_in[0];
    const float* targets = (const float*)d_in[1];
    const float* params  = (const float*)d_in[2];
    const void*  parent  = d_in[3];
    const void*  child   = d_in[4];

    cudaFuncSetAttribute(k_main,
                         cudaFuncAttributeMaxDynamicSharedMemorySize,
                         SMEM_BYTES);

    k_pack<<<1, 1024>>>(parent, child);
    k_main<<<NBLK, BLKT, SMEM_BYTES>>>(logits, targets, params, (float*)d_out);
}